// round 3
// baseline (speedup 1.0000x reference)
#include <cuda_runtime.h>

// DynamicWeightedMSELoss: scalar mean of w * (input - target)^2 where
//   w = 1 - counts[ch][idx]/total[ch] if round(input*10) lands on the
//   [-10.0 .. 10.0 step 0.1] grid, else 1.0.
//
// Grid membership collapses exactly to m = rint(x*10) in [-100,100] since
// steps[ch][k] == (k-100)/10.0f and r == m/10.0f are bit-identical fp32
// computations; off-grid distance >= 0.1 >> 1e-4 tolerance.
//
// This version: branch-free clamped LUT (203 bins/ch, sentinel 1.0 at both
// ends), front-batched U=4 float4 loads per array (8 independent LDG.128 in
// flight per thread), channel-base int4 table in smem, dual accumulators.

#define NBINS    201
#define NCH      5
#define LUTW     203                 // [-101..101] clamped, ends = 1.0
#define LUT_SIZE (LUTW * NCH)        // 1015 floats
#define BLOCK    256
#define GRID     1184                // 8 blocks/SM * 148 SMs
#define U        4

__device__ float        g_partials[GRID];
__device__ unsigned int g_done_count = 0;

__global__ __launch_bounds__(BLOCK, 4)
void fused_wmse_kernel(const float4* __restrict__ in4,
                       const float4* __restrict__ tg4,
                       int nvec, int ntail,
                       const float* __restrict__ in_s,
                       const float* __restrict__ tg_s,
                       const int* __restrict__ counts,
                       float* __restrict__ out, long long n_total) {
    __shared__ float sw[LUT_SIZE];
    __shared__ float s_inv[NCH];
    __shared__ int4  s_bases[NCH];   // per (vec_idx % 5): 4 channel LUT centers

    const int tid  = threadIdx.x;
    const int wid  = tid >> 5;
    const int lane = tid & 31;

    // ---- per-block LUT build (counts: [5,201] int32, L2-hot, ~4KB) ----
    if (wid < NCH) {
        long long s = 0;
        #pragma unroll
        for (int k = lane; k < NBINS; k += 32) s += counts[wid * NBINS + k];
        #pragma unroll
        for (int o = 16; o > 0; o >>= 1)
            s += __shfl_down_sync(0xffffffffu, s, o);
        if (lane == 0) s_inv[wid] = 1.0f / (float)s;
    }
    __syncthreads();
    for (int i = tid; i < LUT_SIZE; i += BLOCK) {
        int ch = i / LUTW;
        int j  = i - ch * LUTW;      // 0..202
        float w = 1.0f;
        if (j > 0 && j < LUTW - 1)
            w = 1.0f - (float)counts[ch * NBINS + (j - 1)] * s_inv[ch];
        sw[i] = w;
    }
    if (tid < NCH) {
        // first element of vec v has channel (4v)%5 = (5 - v%5)%5
        int c0 = (5 - tid) % 5;
        int c1 = (c0 + 1) % 5, c2 = (c0 + 2) % 5, c3 = (c0 + 3) % 5;
        s_bases[tid] = make_int4(c0 * LUTW + 101, c1 * LUTW + 101,
                                 c2 * LUTW + 101, c3 * LUTW + 101);
    }
    __syncthreads();

    // ---- main loop: U=4 front-batched float4 pairs per iteration ----
    float acc0 = 0.0f, acc1 = 0.0f;
    const int stride = GRID * BLOCK;
    const int chunk  = stride * U;
    const int nmain  = nvec - (nvec % chunk);
    const int i0     = blockIdx.x * BLOCK + tid;

    #define TERM(xx, tt, bb, acc) do {                         \
        float d_ = (xx) - (tt);                                \
        int   m_ = __float2int_rn((xx) * 10.0f);               \
        m_ = max(-101, min(101, m_));                          \
        acc = fmaf(sw[(bb) + m_], d_ * d_, acc);               \
    } while (0)

    for (int i = i0; i < nmain; i += chunk) {
        float4 x[U], t[U];
        #pragma unroll
        for (int u = 0; u < U; ++u) x[u] = __ldcs(&in4[i + u * stride]);
        #pragma unroll
        for (int u = 0; u < U; ++u) t[u] = __ldcs(&tg4[i + u * stride]);
        #pragma unroll
        for (int u = 0; u < U; ++u) {
            int  v  = i + u * stride;
            int4 bb = s_bases[v % 5];
            TERM(x[u].x, t[u].x, bb.x, acc0);
            TERM(x[u].y, t[u].y, bb.y, acc1);
            TERM(x[u].z, t[u].z, bb.z, acc0);
            TERM(x[u].w, t[u].w, bb.w, acc1);
        }
    }
    // remainder vec4s (grid-stride, guarded)
    for (int i = nmain + i0; i < nvec; i += stride) {
        float4 x = __ldcs(&in4[i]);
        float4 t = __ldcs(&tg4[i]);
        int4  bb = s_bases[i % 5];
        TERM(x.x, t.x, bb.x, acc0);
        TERM(x.y, t.y, bb.y, acc1);
        TERM(x.z, t.z, bb.z, acc0);
        TERM(x.w, t.w, bb.w, acc1);
    }
    // scalar tail (n % 4 elements), handled once
    if (blockIdx.x == 0 && tid == 0) {
        for (int j = 0; j < ntail; ++j) {
            int e = nvec * 4 + j;
            int bb = (e % 5) * LUTW + 101;
            TERM(in_s[e], tg_s[e], bb, acc0);
        }
    }
    float acc = acc0 + acc1;

    // ---- deterministic block tree-reduce ----
    __shared__ float sred[BLOCK];
    sred[tid] = acc;
    __syncthreads();
    #pragma unroll
    for (int s = BLOCK / 2; s > 0; s >>= 1) {
        if (tid < s) sred[tid] += sred[tid + s];
        __syncthreads();
    }

    // ---- last-block finalize (double accumulation, fixed order) ----
    __shared__ bool s_last;
    if (tid == 0) {
        g_partials[blockIdx.x] = sred[0];
        __threadfence();
        unsigned int prev = atomicAdd(&g_done_count, 1u);
        s_last = (prev == (unsigned int)(gridDim.x - 1));
    }
    __syncthreads();

    if (s_last) {
        __shared__ double sd[BLOCK];
        double a = 0.0;
        for (int i = tid; i < GRID; i += BLOCK) a += (double)g_partials[i];
        sd[tid] = a;
        __syncthreads();
        #pragma unroll
        for (int s = BLOCK / 2; s > 0; s >>= 1) {
            if (tid < s) sd[tid] += sd[tid + s];
            __syncthreads();
        }
        if (tid == 0) {
            out[0] = (float)(sd[0] / (double)n_total);
            g_done_count = 0;   // reset for next graph replay
        }
    }
}

// ---------------------------------------------------------------------------
// Launch: d_in[0]=input [B,5] f32, d_in[1]=target [B,5] f32,
//         d_in[2]=steps [5,201] f32 (unused — exact grid), d_in[3]=counts [5,201] i32
// ---------------------------------------------------------------------------
extern "C" void kernel_launch(void* const* d_in, const int* in_sizes, int n_in,
                              void* d_out, int out_size) {
    const float* input  = (const float*)d_in[0];
    const float* target = (const float*)d_in[1];
    const int*   counts = (const int*)d_in[3];
    float* out = (float*)d_out;

    long long n = in_sizes[0];          // B * 5 elements
    int nvec  = (int)(n / 4);
    int ntail = (int)(n % 4);

    fused_wmse_kernel<<<GRID, BLOCK>>>((const float4*)input,
                                       (const float4*)target,
                                       nvec, ntail, input, target,
                                       counts, out, n);
}